// round 1
// baseline (speedup 1.0000x reference)
#include <cuda_runtime.h>
#include <cuda_bf16.h>

// Spatial-hash neighbor edges.
// Output out[i, j] (i in [start,end), j in [0,n)) = d2(i,j) if
//   j > i  AND  d2 < (min(ri,mr)+min(rj,mr))^2 with mr = 1.5*min(ri,rj)
//   AND ri < 1.0  AND hash-neighbor mask.
// The hash mask is implied by the distance test (threshold < 1 = voxel size,
// so any passing pair is voxel-adjacent and the linear hash matches exactly),
// hence: zero-fill the dense output, then scatter the sparse valid pairs
// found via a 32^3 voxel grid.

#define GRID_DIM   32
#define NUM_CELLS  (GRID_DIM * GRID_DIM * GRID_DIM)   // 32768
#define CAP        32                                  // max points per cell (lambda=0.5)

__device__ int g_counts[NUM_CELLS];
__device__ int g_bucket[NUM_CELLS * CAP];

// ---------------------------------------------------------------------------
// 1. Zero-fill the 128 MB output with 16B stores (HBM-write bound).
// ---------------------------------------------------------------------------
__global__ void zero_out_kernel(float4* __restrict__ out, int n4) {
    int idx = blockIdx.x * blockDim.x + threadIdx.x;
    if (idx < n4) out[idx] = make_float4(0.f, 0.f, 0.f, 0.f);
}

// ---------------------------------------------------------------------------
// 2. Reset the voxel-grid counters (must happen on every graph replay).
// ---------------------------------------------------------------------------
__global__ void zero_counts_kernel() {
    int idx = blockIdx.x * blockDim.x + threadIdx.x;
    if (idx < NUM_CELLS) g_counts[idx] = 0;
}

// ---------------------------------------------------------------------------
// 3. Bucket all points into the voxel grid. Points are uniform in [0,32)^3,
//    and int cast == trunc == floor for positives (matches astype(int32)).
// ---------------------------------------------------------------------------
__global__ void fill_kernel(const float* __restrict__ pts, int n) {
    int j = blockIdx.x * blockDim.x + threadIdx.x;
    if (j >= n) return;
    int vx = (int)pts[3 * j + 0];
    int vy = (int)pts[3 * j + 1];
    int vz = (int)pts[3 * j + 2];
    int c  = (vx * GRID_DIM + vy) * GRID_DIM + vz;
    int slot = atomicAdd(&g_counts[c], 1);
    if (slot < CAP) g_bucket[c * CAP + slot] = j;
}

// ---------------------------------------------------------------------------
// 4. Sparse pair evaluation: one thread per (query i, neighbor-cell k).
//    2048 * 27 = 55296 threads; each scans ~0.5 points on average.
//    All float ops use explicit round-to-nearest intrinsics in the exact
//    order of the reference so threshold comparisons are bit-identical.
// ---------------------------------------------------------------------------
__global__ void pair_kernel(const float* __restrict__ pts,
                            const float* __restrict__ radii,
                            const int* __restrict__ start_p,
                            const int* __restrict__ end_p,
                            float* __restrict__ out, int n) {
    int t = blockIdx.x * blockDim.x + threadIdx.x;
    int start = *start_p;
    int end   = *end_p;

    int irel = t / 27;
    int k    = t - irel * 27;
    int i    = start + irel;
    if (i >= end) return;

    float pix = pts[3 * i + 0];
    float piy = pts[3 * i + 1];
    float piz = pts[3 * i + 2];
    float ri  = radii[i];
    if (!(ri < 1.0f)) return;   // DIS_THRESHOLD

    int vx = (int)pix + (k / 9) - 1;
    int vy = (int)piy + ((k / 3) % 3) - 1;
    int vz = (int)piz + (k % 3) - 1;
    if ((unsigned)vx >= (unsigned)GRID_DIM ||
        (unsigned)vy >= (unsigned)GRID_DIM ||
        (unsigned)vz >= (unsigned)GRID_DIM) return;

    int c   = (vx * GRID_DIM + vy) * GRID_DIM + vz;
    int cnt = min(g_counts[c], CAP);
    long long rowbase = (long long)irel * (long long)n;

    for (int s = 0; s < cnt; s++) {
        int j = g_bucket[c * CAP + s];
        if (j <= i) continue;

        float dx = __fsub_rn(pix, pts[3 * j + 0]);
        float dy = __fsub_rn(piy, pts[3 * j + 1]);
        float dz = __fsub_rn(piz, pts[3 * j + 2]);
        // Match jnp.sum order: (dx*dx + dy*dy) + dz*dz, no FMA contraction.
        float d2 = __fadd_rn(__fadd_rn(__fmul_rn(dx, dx), __fmul_rn(dy, dy)),
                             __fmul_rn(dz, dz));

        float rj = radii[j];
        float m  = fminf(ri, rj);
        float mr = __fmul_rn(m, 1.5f);          // max_r = min(ri,rj)*1.5
        float a  = fminf(ri, mr);
        float b  = fminf(rj, mr);
        float tt = __fadd_rn(a, b);
        float srq = __fmul_rn(tt, tt);          // EDGE_DIST_SCALE = 1.0 exact

        if (d2 < srq) out[rowbase + j] = d2;
    }
}

// ---------------------------------------------------------------------------
extern "C" void kernel_launch(void* const* d_in, const int* in_sizes, int n_in,
                              void* d_out, int out_size) {
    const float* pts   = (const float*)d_in[0];
    const float* radii = (const float*)d_in[1];
    const int*   sp    = (const int*)d_in[2];
    const int*   ep    = (const int*)d_in[3];

    int n     = in_sizes[0] / 3;       // 16384
    int chunk = out_size / n;          // 2048
    int n4    = out_size / 4;          // out_size divisible by 4

    zero_out_kernel<<<(n4 + 255) / 256, 256>>>((float4*)d_out, n4);
    zero_counts_kernel<<<(NUM_CELLS + 255) / 256, 256>>>();
    fill_kernel<<<(n + 255) / 256, 256>>>(pts, n);

    int T = chunk * 27;
    pair_kernel<<<(T + 127) / 128, 128>>>(pts, radii, sp, ep, (float*)d_out, n);
}